// round 9
// baseline (speedup 1.0000x reference)
#include <cuda_runtime.h>
#include <cuda_fp16.h>
#include <cstdint>

#define DT 0.1f
#define TAU_HP 12.3f
#define TAU_LP 2.3f

#define N_NEURONS_MAX 200000
#define N_EDGES_MAX   7200000      // 6.4M real + up to 800k pad slots
#define N_TM1_MAX     25000
#define STEPS_MAX     50

#define CHUNK      51200           // sources per chunk (16-bit local idx)
#define NCHUNK     4
#define CHUNK_B    (CHUNK * 2)     // bytes per staged fp16 chunk
#define GRID_RUN   148
#define NCLUSTERS  74
#define TPB        1024
#define GROUPS     256             // 4 lanes per row-group
#define MAX_WAVES  10              // ceil(ceil(175000/74)/256)
#define PART_OFF   (2 * CHUNK_B)   // smem offset of partial-sum array
#define PART_MAX   (MAX_WAVES * GROUPS)
#define SMEM_RUN   (PART_OFF + PART_MAX * 4)

// ---------------- device scratch (no allocations allowed) ----------------
__device__ int      g_counts[NCHUNK * N_NEURONS_MAX];
__device__ int      g_seg_ptr[NCHUNK * N_NEURONS_MAX + 1];
__device__ int      g_cursor[NCHUNK * N_NEURONS_MAX];
__device__ int      g_block_sums[512];
__device__ unsigned g_bar1, g_bar2, g_bar3;
__device__ unsigned g_flags[GRID_RUN];
__device__ __align__(16) unsigned g_epk[N_EDGES_MAX];   // packed {w_fp16, src16}
__device__ __align__(16) float  g_vbuf[2][N_NEURONS_MAX];
__device__ __align__(16) __half g_rbuf[2][N_NEURONS_MAX];
__device__ float    g_table[(STEPS_MAX + 1) * N_TM1_MAX];

// ---------------- helpers ----------------
__device__ __forceinline__ uint32_t smem_u32(const void* p) {
    uint32_t a;
    asm("{ .reg .u64 t; cvta.to.shared.u64 t, %1; cvt.u32.u64 %0, t; }"
        : "=r"(a) : "l"(p));
    return a;
}
__device__ __forceinline__ void cp16(uint32_t dst, const void* src) {
    asm volatile("cp.async.cg.shared.global [%0], [%1], 16;"
                 :: "r"(dst), "l"(src) : "memory");
}
__device__ __forceinline__ void cp_commit() {
    asm volatile("cp.async.commit_group;" ::: "memory");
}
template <int N> __device__ __forceinline__ void cp_wait() {
    asm volatile("cp.async.wait_group %0;" :: "n"(N) : "memory");
}
__device__ __forceinline__ unsigned cluster_rank() {
    unsigned r; asm("mov.u32 %0, %%cluster_ctarank;" : "=r"(r)); return r;
}
__device__ __forceinline__ float dsmem_f32(uint32_t local_addr, unsigned rank) {
    uint32_t ra; float v;
    asm("mapa.shared::cluster.u32 %0, %1, %2;" : "=r"(ra) : "r"(local_addr), "r"(rank));
    asm volatile("ld.shared::cluster.f32 %0, [%1];" : "=f"(v) : "r"(ra) : "memory");
    return v;
}
__device__ __forceinline__ void grid_barrier(int bid, int tid, unsigned target) {
    __syncthreads();
    if (tid == 0)
        asm volatile("st.global.release.gpu.b32 [%0], %1;"
                     :: "l"(&g_flags[bid]), "r"(target) : "memory");
    if (tid < GRID_RUN) {
        unsigned v;
        do {
            asm volatile("ld.global.acquire.gpu.b32 %0, [%1];"
                         : "=r"(v) : "l"(&g_flags[tid]) : "memory");
        } while (v < target);
    }
    __syncthreads();
}

// ---------------- setup kernels ----------------

__global__ void k_zero(int nseg, int n_neurons) {
    int i = blockIdx.x * blockDim.x + threadIdx.x;
    if (i < nseg) g_counts[i] = 0;
    if (i < n_neurons) { g_vbuf[0][i] = 0.0f; g_rbuf[0][i] = __float2half(0.0f); }
    if (i < GRID_RUN) g_flags[i] = 0;
    if (i == 0) { g_bar1 = 0; g_bar2 = 0; g_bar3 = 0; }
}

// blocks [0,tb): Tm1 filter trajectory; rest: per-(target,chunk) histogram
__global__ void k_tm1hist(const float* __restrict__ x,
                          const int* __restrict__ src, const int* __restrict__ tgt,
                          int n_tm1, int steps, int n_edges, int tb) {
    int bid = blockIdx.x;
    if (bid < tb) {
        int i = bid * blockDim.x + threadIdx.x;
        if (i >= n_tm1) return;
        float f = 0.0f, tv = 0.0f;
        for (int s = 0; s < steps; s++) {
            g_table[s * n_tm1 + i] = tv;
            float xi = x[(long long)s * n_tm1 + i];
            float hp = xi - f;
            f  += DT * hp / TAU_HP;
            tv += DT * (fmaxf(hp, 0.0f) - tv) / TAU_LP;
        }
        g_table[steps * n_tm1 + i] = tv;
    } else {
        int e = (bid - tb) * blockDim.x + threadIdx.x;
        if (e >= n_edges) return;
        int t = tgt[e];
        if (t >= n_tm1) {
            int c = src[e] / CHUNK;
            atomicAdd(&g_counts[NCHUNK * t + c], 1);
        }
    }
}

// Fused scan (with even-padding) + pad-zero + scatter fill.
// 196 blocks of 1024, all co-resident (2/SM forced), 3 grid barriers.
__global__ void __launch_bounds__(1024, 2)
k_scanfill(const int* __restrict__ src, const int* __restrict__ tgt,
           const float* __restrict__ w,
           int n_edges, int n_tm1, int nseg, int nblocks) {
    __shared__ int sh[1024];
    __shared__ int s_off;
    int tid = threadIdx.x, bid = blockIdx.x;

    // phase A: 4 histogram entries per thread, sizes padded to even
    int base = bid * 4096 + tid * 4;
    int p0 = (base + 0 < nseg) ? ((g_counts[base + 0] + 1) & ~1) : 0;
    int p1 = (base + 1 < nseg) ? ((g_counts[base + 1] + 1) & ~1) : 0;
    int p2 = (base + 2 < nseg) ? ((g_counts[base + 2] + 1) & ~1) : 0;
    int p3 = (base + 3 < nseg) ? ((g_counts[base + 3] + 1) & ~1) : 0;
    int tot = p0 + p1 + p2 + p3;
    sh[tid] = tot;
    __syncthreads();
    #pragma unroll
    for (int o = 1; o < 1024; o <<= 1) {
        int v = (tid >= o) ? sh[tid - o] : 0;
        __syncthreads();
        sh[tid] += v;
        __syncthreads();
    }
    int incl = sh[tid];
    int excl = incl - tot;
    if (tid == 1023) g_block_sums[bid] = incl;

    __threadfence(); __syncthreads();
    if (tid == 0) {
        atomicAdd(&g_bar1, 1);
        while (((volatile unsigned*)&g_bar1)[0] < (unsigned)nblocks) {}
        __threadfence();
    }
    __syncthreads();

    if (tid < 32) {
        int p = 0;
        for (int j = tid; j < bid; j += 32) p += g_block_sums[j];
        #pragma unroll
        for (int o = 16; o; o >>= 1) p += __shfl_xor_sync(0xffffffffu, p, o);
        if (tid == 0) s_off = p;
    }
    __syncthreads();
    int off = s_off + excl;
    if (base + 0 < nseg) { g_seg_ptr[base + 0] = off;                g_cursor[base + 0] = off; }
    if (base + 1 < nseg) { g_seg_ptr[base + 1] = off + p0;           g_cursor[base + 1] = off + p0; }
    if (base + 2 < nseg) { g_seg_ptr[base + 2] = off + p0 + p1;      g_cursor[base + 2] = off + p0 + p1; }
    if (base + 3 < nseg) { g_seg_ptr[base + 3] = off + p0 + p1 + p2; g_cursor[base + 3] = off + p0 + p1 + p2; }
    if (bid == nblocks - 1 && tid == 1023) g_seg_ptr[nseg] = s_off + incl;

    __threadfence(); __syncthreads();
    if (tid == 0) {
        atomicAdd(&g_bar2, 1);
        while (((volatile unsigned*)&g_bar2)[0] < (unsigned)nblocks) {}
        __threadfence();
    }
    __syncthreads();

    // phase C0: zero the last slot of every segment (covers the pad slot when
    // the real count is odd; overwritten by a real edge when even)
    int gsz = nblocks * 1024;
    for (int i = bid * 1024 + tid; i < nseg; i += gsz) {
        int e0 = g_seg_ptr[i + 1];
        int s0 = g_seg_ptr[i];
        if (e0 > s0) g_epk[e0 - 1] = 0;   // {w=+0.0h, src=0} -> contributes 0
    }

    __threadfence(); __syncthreads();
    if (tid == 0) {
        atomicAdd(&g_bar3, 1);
        while (((volatile unsigned*)&g_bar3)[0] < (unsigned)nblocks) {}
        __threadfence();
    }
    __syncthreads();

    // phase C: scatter-fill packed edges
    for (int e = bid * 1024 + tid; e < n_edges; e += gsz) {
        int tt = tgt[e];
        if (tt >= n_tm1) {
            int s = src[e];
            int c = s / CHUNK;
            int pos = atomicAdd(&g_cursor[NCHUNK * tt + c], 1);
            unsigned short hw = __half_as_ushort(__float2half_rn(w[e]));
            g_epk[pos] = ((unsigned)hw << 16) | (unsigned)(s - c * CHUNK);
        }
    }
}

// ---------------- persistent 50-step kernel ----------------
// Cluster(2): rank q stages source chunks {2q, 2q+1} (100KB each, double-
// buffered cp.async) and computes partial sums over its source half for ALL
// 2366 cluster rows; partials exchanged via DSMEM. Row segment metadata
// (base + two 16-bit padded lengths) lives in registers for the whole run.
// Grid-wide flag barrier between steps (148 blocks, all co-resident).
__global__ void __launch_bounds__(TPB, 1) __cluster_dims__(2, 1, 1)
k_run(float* __restrict__ out,
      const float* __restrict__ tau, const float* __restrict__ vrest,
      int n_neurons, int n_tm1, int steps) {
    extern __shared__ __align__(16) unsigned char smem_raw[];
    __half* sbuf = (__half*)smem_raw;                 // 2 x CHUNK halves
    float*  spart = (float*)(smem_raw + PART_OFF);    // cluster-row partials
    uint32_t sbase = smem_u32(smem_raw);

    int tid = threadIdx.x, bid = blockIdx.x;
    int group = tid >> 2, lane = tid & 3;
    unsigned q = cluster_rank();
    int cid = bid >> 1;

    int rows_total = n_neurons - n_tm1;
    int perC = (rows_total + NCLUSTERS - 1) / NCLUSTERS;     // 2366
    int r0C = n_tm1 + cid * perC;
    int r1C = min(n_neurons, r0C + perC);

    // row metadata in registers for the whole run
    int      mbase[MAX_WAVES];
    unsigned mlens[MAX_WAVES];
    #pragma unroll
    for (int w = 0; w < MAX_WAVES; w++) {
        int row = r0C + w * GROUPS + group;
        if (row < r1C) {
            int a0 = g_seg_ptr[4 * row + 2 * q];
            int a1 = g_seg_ptr[4 * row + 2 * q + 1];
            int a2 = g_seg_ptr[4 * row + 2 * q + 2];
            mbase[w] = a0;
            mlens[w] = (unsigned)(a1 - a0) | ((unsigned)(a2 - a1) << 16);
        } else { mbase[w] = 0; mlens[w] = 0; }
    }

    int cA = 2 * (int)q, cB = cA + 1;
    float acc[MAX_WAVES];

    for (int s = 0; s < steps; s++) {
        const __half* rold = &g_rbuf[s & 1][0];
        __half*       rnew = &g_rbuf[(s + 1) & 1][0];
        const float*  vold = &g_vbuf[s & 1][0];
        float*        vnew = &g_vbuf[(s + 1) & 1][0];

        // stage my two source chunks (async)
        {
            int csz = min(CHUNK, n_neurons - cA * CHUNK);
            int n16 = (csz * 2) >> 4;
            const char* sp = (const char*)(rold + cA * CHUNK);
            for (int i = tid; i < n16; i += TPB) cp16(sbase + i * 16, sp + i * 16);
        }
        cp_commit();
        {
            int csz = min(CHUNK, n_neurons - cB * CHUNK);
            int n16 = (csz * 2) >> 4;
            const char* sp = (const char*)(rold + cB * CHUNK);
            for (int i = tid; i < n16; i += TPB) cp16(sbase + CHUNK_B + i * 16, sp + i * 16);
        }
        cp_commit();

        // Tm1 refresh overlaps the copies
        {
            const float* tn = g_table + (size_t)(s + 1) * n_tm1;
            int tper = (n_tm1 + GRID_RUN - 1) / GRID_RUN;
            int t0 = bid * tper, t1 = min(n_tm1, t0 + tper);
            for (int i = t0 + tid; i < t1; i += TPB) {
                float tv = tn[i];
                vnew[i] = tv;
                rnew[i] = __float2half(fmaxf(tv, 0.0f));
            }
        }

        // chunk A
        cp_wait<1>(); __syncthreads();
        #pragma unroll
        for (int w = 0; w < MAX_WAVES; w++) {
            int len = (int)(mlens[w] & 0xFFFFu);
            int s0 = mbase[w];
            int e0 = s0 + len;
            float sum = 0.0f;
            for (int j = s0 + lane * 2; j < e0; j += 8) {
                uint2 uu = __ldg((const uint2*)&g_epk[j]);
                sum += __half2float(__ushort_as_half((unsigned short)(uu.x >> 16)))
                     * __half2float(sbuf[uu.x & 0xFFFFu]);
                sum += __half2float(__ushort_as_half((unsigned short)(uu.y >> 16)))
                     * __half2float(sbuf[uu.y & 0xFFFFu]);
            }
            acc[w] = sum;
        }
        // chunk B
        cp_wait<0>(); __syncthreads();
        #pragma unroll
        for (int w = 0; w < MAX_WAVES; w++) {
            int lenA = (int)(mlens[w] & 0xFFFFu);
            int len = (int)(mlens[w] >> 16);
            int s0 = mbase[w] + lenA;
            int e0 = s0 + len;
            const __half* sr = sbuf + CHUNK;
            float sum = 0.0f;
            for (int j = s0 + lane * 2; j < e0; j += 8) {
                uint2 uu = __ldg((const uint2*)&g_epk[j]);
                sum += __half2float(__ushort_as_half((unsigned short)(uu.x >> 16)))
                     * __half2float(sr[uu.x & 0xFFFFu]);
                sum += __half2float(__ushort_as_half((unsigned short)(uu.y >> 16)))
                     * __half2float(sr[uu.y & 0xFFFFu]);
            }
            acc[w] += sum;
        }

        // write per-row partials for this source half
        #pragma unroll
        for (int w = 0; w < MAX_WAVES; w++) {
            float sum = acc[w];
            sum += __shfl_xor_sync(0xffffffffu, sum, 2);
            sum += __shfl_xor_sync(0xffffffffu, sum, 1);
            if (lane == 0) spart[w * GROUPS + group] = sum;
        }
        asm volatile("barrier.cluster.arrive.aligned;" ::: "memory");
        asm volatile("barrier.cluster.wait.aligned;" ::: "memory");

        // finalize my half of the cluster rows: local + peer partial
        {
            int halfC = (perC + 1) >> 1;
            int i0 = (int)q * halfC;
            int i1 = min(perC, i0 + halfC);
            for (int i = i0 + tid; i < i1; i += TPB) {
                int row = r0C + i;
                if (row >= n_neurons) break;
                float psum = spart[i]
                           + dsmem_f32(sbase + PART_OFF + i * 4, q ^ 1u);
                float vv = vold[row];
                float vn = vv + DT * ((psum - vv + vrest[row]) / tau[row]);
                vnew[row] = vn;
                rnew[row] = __float2half(fmaxf(vn, 0.0f));
            }
        }

        grid_barrier(bid, tid, (unsigned)(s + 1));
    }

    // epilogue: write output (final barrier already passed)
    {
        int oper = (n_neurons + GRID_RUN - 1) / GRID_RUN;
        int o0 = bid * oper, o1 = min(n_neurons, o0 + oper);
        const float* vfin = &g_vbuf[steps & 1][0];
        const float* tfin = g_table + (size_t)(steps - 1) * n_tm1;
        for (int i = o0 + tid; i < o1; i += TPB)
            out[i] = (i < n_tm1) ? tfin[i] : vfin[i];
    }
}

// ---------------- launch ----------------

extern "C" void kernel_launch(void* const* d_in, const int* in_sizes, int n_in,
                              void* d_out, int out_size) {
    const float* tm1_input = (const float*)d_in[0];
    const float* weights   = (const float*)d_in[1];
    const float* tau       = (const float*)d_in[2];
    const float* vrest     = (const float*)d_in[3];
    const int*   src       = (const int*)  d_in[4];
    const int*   tgt       = (const int*)  d_in[5];

    const int n_tm1     = 25000;
    const int n_edges   = in_sizes[1];
    const int n_neurons = in_sizes[2];
    const int steps     = in_sizes[0] / n_tm1;

    const int nseg = NCHUNK * n_neurons;

    cudaFuncSetAttribute(k_run, cudaFuncAttributeMaxDynamicSharedMemorySize, SMEM_RUN);

    k_zero<<<(nseg + 255) / 256, 256>>>(nseg, n_neurons);
    int tb = (n_tm1 + 255) / 256;
    int eb = (n_edges + 255) / 256;
    k_tm1hist<<<tb + eb, 256>>>(tm1_input, src, tgt, n_tm1, steps, n_edges, tb);
    int scan_blocks = (nseg + 4095) / 4096;           // 196, all co-resident
    k_scanfill<<<scan_blocks, 1024>>>(src, tgt, weights, n_edges, n_tm1,
                                      nseg, scan_blocks);

    k_run<<<GRID_RUN, TPB, SMEM_RUN>>>((float*)d_out, tau, vrest,
                                       n_neurons, n_tm1, steps);
}

// round 10
// speedup vs baseline: 1.1512x; 1.1512x over previous
#include <cuda_runtime.h>
#include <cuda_fp16.h>
#include <cstdint>

#define DT 0.1f
#define TAU_HP 12.3f
#define TAU_LP 2.3f

#define N_NEURONS_MAX 200000
#define N_EDGES_MAX   7200000      // 5.6M kept + <=700k pad slots
#define N_TM1_MAX     25000
#define STEPS_MAX     50

#define CHUNK      50000           // sources per chunk (16-bit local idx, exact x4)
#define NCHUNK     4
#define CHUNK_B    (CHUNK * 2)     // 100000 B staged fp16 chunk (16B multiple)
#define GRID_STEP  148
#define TPB_STEP   1024
#define GROUPS     256             // 4 lanes per row-group
#define MAX_WAVES  5               // ceil(ceil(175000/148)/256)

// ---------------- device scratch (no allocations allowed) ----------------
__device__ int      g_counts[NCHUNK * N_NEURONS_MAX];
__device__ int      g_seg_ptr[NCHUNK * N_NEURONS_MAX + 1];
__device__ int      g_cursor[NCHUNK * N_NEURONS_MAX];
__device__ int      g_block_sums[512];
__device__ unsigned g_bar1, g_bar2, g_bar3;
__device__ __align__(16) unsigned g_epk[N_EDGES_MAX];   // packed {w_fp16, src16}
__device__ __align__(16) float  g_vbuf[2][N_NEURONS_MAX];
__device__ __align__(16) __half g_rbuf[2][N_NEURONS_MAX];
__device__ float    g_kA[N_NEURONS_MAX];                // DT/tau
__device__ float    g_kC[N_NEURONS_MAX];                // DT/tau * vrest
__device__ float    g_table[(STEPS_MAX + 1) * N_TM1_MAX];

// ---------------- helpers ----------------
__device__ __forceinline__ uint32_t smem_u32(const void* p) {
    uint32_t a;
    asm("{ .reg .u64 t; cvta.to.shared.u64 t, %1; cvt.u32.u64 %0, t; }"
        : "=r"(a) : "l"(p));
    return a;
}
__device__ __forceinline__ void mbar_init(uint32_t mbar, unsigned cnt) {
    asm volatile("mbarrier.init.shared.b64 [%0], %1;" :: "r"(mbar), "r"(cnt) : "memory");
}
__device__ __forceinline__ void mbar_expect(uint32_t mbar, unsigned bytes) {
    asm volatile("mbarrier.arrive.expect_tx.shared.b64 _, [%0], %1;"
                 :: "r"(mbar), "r"(bytes) : "memory");
}
__device__ __forceinline__ void bulk_cp(uint32_t dst, const void* src,
                                        unsigned bytes, uint32_t mbar) {
    asm volatile("cp.async.bulk.shared::cta.global.mbarrier::complete_tx::bytes "
                 "[%0], [%1], %2, [%3];"
                 :: "r"(dst), "l"(src), "r"(bytes), "r"(mbar) : "memory");
}
__device__ __forceinline__ void mbar_wait(uint32_t mbar, int phase) {
    asm volatile(
        "{\n\t.reg .pred P;\n\t"
        "W%=:\n\t"
        "mbarrier.try_wait.parity.acquire.cta.shared::cta.b64 P, [%0], %1, 0x989680;\n\t"
        "@P bra D%=;\n\t"
        "bra W%=;\n\t"
        "D%=:\n\t}"
        :: "r"(mbar), "r"(phase) : "memory");
}

// ---------------- setup kernels ----------------

__global__ void k_zero(int nseg, int n_neurons) {
    int i = blockIdx.x * blockDim.x + threadIdx.x;
    if (i < nseg) g_counts[i] = 0;
    if (i < n_neurons) { g_vbuf[0][i] = 0.0f; g_rbuf[0][i] = __float2half(0.0f); }
    if (i == 0) { g_bar1 = 0; g_bar2 = 0; g_bar3 = 0; }
}

// blocks [0,tb): Tm1 trajectory; [tb,tb+kb): kA/kC precompute; rest: histogram
__global__ void k_tm1hist(const float* __restrict__ x,
                          const float* __restrict__ tau, const float* __restrict__ vrest,
                          const int* __restrict__ src, const int* __restrict__ tgt,
                          int n_tm1, int steps, int n_edges, int n_neurons,
                          int tb, int kb) {
    int bid = blockIdx.x;
    if (bid < tb) {
        int i = bid * blockDim.x + threadIdx.x;
        if (i >= n_tm1) return;
        float f = 0.0f, tv = 0.0f;
        for (int s = 0; s < steps; s++) {
            g_table[s * n_tm1 + i] = tv;
            float xi = x[(long long)s * n_tm1 + i];
            float hp = xi - f;
            f  += DT * hp / TAU_HP;
            tv += DT * (fmaxf(hp, 0.0f) - tv) / TAU_LP;
        }
        g_table[steps * n_tm1 + i] = tv;
    } else if (bid < tb + kb) {
        int i = (bid - tb) * blockDim.x + threadIdx.x;
        if (i < n_neurons) {
            float a = DT / tau[i];
            g_kA[i] = a;
            g_kC[i] = a * vrest[i];
        }
    } else {
        int e = (bid - tb - kb) * blockDim.x + threadIdx.x;
        if (e >= n_edges) return;
        int t = tgt[e];
        if (t >= n_tm1) {
            int c = src[e] / CHUNK;
            atomicAdd(&g_counts[NCHUNK * t + c], 1);
        }
    }
}

// Fused scan (even-padded sizes) + pad-zero + scatter fill.
// 196 blocks of 1024, all co-resident (2/SM forced), 3 grid barriers.
__global__ void __launch_bounds__(1024, 2)
k_scanfill(const int* __restrict__ src, const int* __restrict__ tgt,
           const float* __restrict__ w,
           int n_edges, int n_tm1, int nseg, int nblocks) {
    __shared__ int sh[1024];
    __shared__ int s_off;
    int tid = threadIdx.x, bid = blockIdx.x;

    // phase A: 4 histogram entries per thread, sizes padded to even
    int base = bid * 4096 + tid * 4;
    int p0 = (base + 0 < nseg) ? ((g_counts[base + 0] + 1) & ~1) : 0;
    int p1 = (base + 1 < nseg) ? ((g_counts[base + 1] + 1) & ~1) : 0;
    int p2 = (base + 2 < nseg) ? ((g_counts[base + 2] + 1) & ~1) : 0;
    int p3 = (base + 3 < nseg) ? ((g_counts[base + 3] + 1) & ~1) : 0;
    int tot = p0 + p1 + p2 + p3;
    sh[tid] = tot;
    __syncthreads();
    #pragma unroll
    for (int o = 1; o < 1024; o <<= 1) {
        int v = (tid >= o) ? sh[tid - o] : 0;
        __syncthreads();
        sh[tid] += v;
        __syncthreads();
    }
    int incl = sh[tid];
    int excl = incl - tot;
    if (tid == 1023) g_block_sums[bid] = incl;

    __threadfence(); __syncthreads();
    if (tid == 0) {
        atomicAdd(&g_bar1, 1);
        while (((volatile unsigned*)&g_bar1)[0] < (unsigned)nblocks) {}
        __threadfence();
    }
    __syncthreads();

    if (tid < 32) {
        int p = 0;
        for (int j = tid; j < bid; j += 32) p += g_block_sums[j];
        #pragma unroll
        for (int o = 16; o; o >>= 1) p += __shfl_xor_sync(0xffffffffu, p, o);
        if (tid == 0) s_off = p;
    }
    __syncthreads();
    int off = s_off + excl;
    if (base + 0 < nseg) { g_seg_ptr[base + 0] = off;                g_cursor[base + 0] = off; }
    if (base + 1 < nseg) { g_seg_ptr[base + 1] = off + p0;           g_cursor[base + 1] = off + p0; }
    if (base + 2 < nseg) { g_seg_ptr[base + 2] = off + p0 + p1;      g_cursor[base + 2] = off + p0 + p1; }
    if (base + 3 < nseg) { g_seg_ptr[base + 3] = off + p0 + p1 + p2; g_cursor[base + 3] = off + p0 + p1 + p2; }
    if (bid == nblocks - 1 && tid == 1023) g_seg_ptr[nseg] = s_off + incl;

    __threadfence(); __syncthreads();
    if (tid == 0) {
        atomicAdd(&g_bar2, 1);
        while (((volatile unsigned*)&g_bar2)[0] < (unsigned)nblocks) {}
        __threadfence();
    }
    __syncthreads();

    // phase C0: zero the last slot of every non-empty segment (covers the pad
    // slot when the real count is odd; overwritten by a real edge when even)
    int gsz = nblocks * 1024;
    for (int i = bid * 1024 + tid; i < nseg; i += gsz) {
        int s0 = g_seg_ptr[i];
        int e0 = g_seg_ptr[i + 1];
        if (e0 > s0) g_epk[e0 - 1] = 0;   // {w=+0.0h, src=0} -> contributes 0
    }

    __threadfence(); __syncthreads();
    if (tid == 0) {
        atomicAdd(&g_bar3, 1);
        while (((volatile unsigned*)&g_bar3)[0] < (unsigned)nblocks) {}
        __threadfence();
    }
    __syncthreads();

    // phase C: scatter-fill packed edges
    for (int e = bid * 1024 + tid; e < n_edges; e += gsz) {
        int tt = tgt[e];
        if (tt >= n_tm1) {
            int s = src[e];
            int c = s / CHUNK;
            int pos = atomicAdd(&g_cursor[NCHUNK * tt + c], 1);
            unsigned short hw = __half_as_ushort(__float2half_rn(w[e]));
            g_epk[pos] = ((unsigned)hw << 16) | (unsigned)(s - c * CHUNK);
        }
    }
}

// ---------------- per-step kernel ----------------
// 148 blocks x 1024. 4 source chunks of 100KB fp16, double-buffered via
// cp.async.bulk + mbarrier (stage c+2 overlaps compute of c). Segments are
// even-padded so each lane reads 2 packed edges per LDG.64 (uint2).
__global__ void __launch_bounds__(TPB_STEP, 1)
k_step(const float*  __restrict__ vold, float* __restrict__ vnew,
       const __half* __restrict__ rold, __half* __restrict__ rnew,
       const float*  __restrict__ table_next,
       int n_neurons, int n_tm1) {
    extern __shared__ __align__(16) unsigned char smem_raw[];
    __half* sbuf = (__half*)smem_raw;                   // 2 x CHUNK halves
    uint32_t smem_base = smem_u32(smem_raw);
    uint32_t mbar = smem_base + 2 * CHUNK_B;            // 2 mbarriers

    int tid = threadIdx.x, bid = blockIdx.x;
    int group = tid >> 2, lane = tid & 3;

    if (tid == 0) {
        mbar_init(mbar, 1);
        mbar_init(mbar + 8, 1);
        asm volatile("fence.proxy.async.shared::cta;" ::: "memory");
    }
    __syncthreads();

    // kick off chunks 0 and 1
    if (tid == 0) {
        mbar_expect(mbar, CHUNK_B);
        bulk_cp(smem_base, rold, CHUNK_B, mbar);
    } else if (tid == 32) {
        mbar_expect(mbar + 8, CHUNK_B);
        bulk_cp(smem_base + CHUNK_B, rold + CHUNK, CHUNK_B, mbar + 8);
    }

    // Tm1 refresh overlaps the copies
    {
        int tper = (n_tm1 + GRID_STEP - 1) / GRID_STEP;
        int t0 = bid * tper, t1 = min(n_tm1, t0 + tper);
        for (int i = t0 + tid; i < t1; i += TPB_STEP) {
            float tv = table_next[i];
            vnew[i] = tv;
            rnew[i] = __float2half(fmaxf(tv, 0.0f));
        }
    }

    int rows = n_neurons - n_tm1;
    int per = (rows + GRID_STEP - 1) / GRID_STEP;
    int r0 = n_tm1 + bid * per;
    int r1 = min(n_neurons, r0 + per);

    float acc[MAX_WAVES];
    #pragma unroll
    for (int w = 0; w < MAX_WAVES; w++) acc[w] = 0.0f;

    #pragma unroll
    for (int c = 0; c < NCHUNK; c++) {
        int b = c & 1;
        mbar_wait(mbar + b * 8, (c >> 1) & 1);
        const __half* sr = sbuf + b * CHUNK;

        #pragma unroll
        for (int w = 0; w < MAX_WAVES; w++) {
            int row = r0 + w * GROUPS + group;
            if (row >= r1) break;
            int s = __ldg(&g_seg_ptr[(row << 2) + c]);
            int e = __ldg(&g_seg_ptr[(row << 2) + c + 1]);
            float sum = 0.0f;
            // even-padded segment, even start -> aligned LDG.64, 2 edges/lane
            for (int j = s + lane * 2; j < e; j += 8) {
                uint2 uu = __ldg((const uint2*)&g_epk[j]);
                sum += __half2float(__ushort_as_half((unsigned short)(uu.x >> 16)))
                     * __half2float(sr[uu.x & 0xFFFFu]);
                sum += __half2float(__ushort_as_half((unsigned short)(uu.y >> 16)))
                     * __half2float(sr[uu.y & 0xFFFFu]);
            }
            acc[w] += sum;
        }
        __syncthreads();   // all groups done reading buffer b

        if (c + 2 < NCHUNK && tid == 0) {
            mbar_expect(mbar + b * 8, CHUNK_B);
            bulk_cp(smem_base + b * CHUNK_B, rold + (c + 2) * CHUNK, CHUNK_B,
                    mbar + b * 8);
        }
    }

    // finalize rows: vn = v + kA*(sum - v) + kC
    #pragma unroll
    for (int w = 0; w < MAX_WAVES; w++) {
        int row = r0 + w * GROUPS + group;
        if (row >= r1) break;
        float sum = acc[w];
        sum += __shfl_xor_sync(0xffffffffu, sum, 2);
        sum += __shfl_xor_sync(0xffffffffu, sum, 1);
        if (lane == 0) {
            float vv = vold[row];
            float vn = fmaf(g_kA[row], sum - vv, vv) + g_kC[row];
            vnew[row] = vn;
            rnew[row] = __float2half(fmaxf(vn, 0.0f));
        }
    }
}

__global__ void k_out(float* __restrict__ out, const float* __restrict__ vfinal,
                      int n, int n_tm1, int steps) {
    int i = blockIdx.x * blockDim.x + threadIdx.x;
    if (i >= n) return;
    out[i] = (i < n_tm1) ? g_table[(steps - 1) * n_tm1 + i] : vfinal[i];
}

// ---------------- launch ----------------

extern "C" void kernel_launch(void* const* d_in, const int* in_sizes, int n_in,
                              void* d_out, int out_size) {
    const float* tm1_input = (const float*)d_in[0];
    const float* weights   = (const float*)d_in[1];
    const float* tau       = (const float*)d_in[2];
    const float* vrest     = (const float*)d_in[3];
    const int*   src       = (const int*)  d_in[4];
    const int*   tgt       = (const int*)  d_in[5];

    const int n_tm1     = 25000;
    const int n_edges   = in_sizes[1];
    const int n_neurons = in_sizes[2];
    const int steps     = in_sizes[0] / n_tm1;

    const int nseg = NCHUNK * n_neurons;
    const int smem_bytes = 2 * CHUNK_B + 32;          // 2 buffers + mbarriers

    cudaFuncSetAttribute(k_step, cudaFuncAttributeMaxDynamicSharedMemorySize, smem_bytes);

    k_zero<<<(nseg + 255) / 256, 256>>>(nseg, n_neurons);
    int tb = (n_tm1 + 255) / 256;
    int kb = (n_neurons + 255) / 256;
    int eb = (n_edges + 255) / 256;
    k_tm1hist<<<tb + kb + eb, 256>>>(tm1_input, tau, vrest, src, tgt,
                                     n_tm1, steps, n_edges, n_neurons, tb, kb);
    int scan_blocks = (nseg + 4095) / 4096;           // 196, all co-resident
    k_scanfill<<<scan_blocks, 1024>>>(src, tgt, weights, n_edges, n_tm1,
                                      nseg, scan_blocks);

    float*  vbase = nullptr;
    __half* rbase = nullptr;
    float*  tbl   = nullptr;
    cudaGetSymbolAddress((void**)&vbase, g_vbuf);
    cudaGetSymbolAddress((void**)&rbase, g_rbuf);
    cudaGetSymbolAddress((void**)&tbl,   g_table);

    for (int st = 0; st < steps; st++) {
        const float*  vold = vbase + (size_t)(st & 1) * N_NEURONS_MAX;
        float*        vnew = vbase + (size_t)((st + 1) & 1) * N_NEURONS_MAX;
        const __half* rold = rbase + (size_t)(st & 1) * N_NEURONS_MAX;
        __half*       rnew = rbase + (size_t)((st + 1) & 1) * N_NEURONS_MAX;
        const float*  table_next = tbl + (size_t)(st + 1) * n_tm1;
        k_step<<<GRID_STEP, TPB_STEP, smem_bytes>>>(vold, vnew, rold, rnew,
                                                    table_next, n_neurons, n_tm1);
    }

    const float* vfinal = vbase + (size_t)(steps & 1) * N_NEURONS_MAX;
    k_out<<<(out_size + 255) / 256, 256>>>((float*)d_out, vfinal,
                                           out_size, n_tm1, steps);
}